// round 15
// baseline (speedup 1.0000x reference)
#include <cuda_runtime.h>
#include <cuda_fp16.h>
#include <cstdint>
#include <math.h>

#define NTOK 8192
#define DDIM 1024
#define FDIM 1024
#define NEXP 8
#define NGRP 9
#define MAT  (DDIM * FDIM)

// ---------------- scratch (device globals; no runtime allocation) ----------
__device__ __half g_wgT16[NEXP * MAT];   // [e][f][d]  (B^T for GEMM1 gate)
__device__ __half g_wuT16[NEXP * MAT];   // [e][f][d]
__device__ __half g_wdT16[NEXP * MAT];   // [e][d][f]  (B^T for GEMM2)
__device__ __half g_sgT16[MAT];
__device__ __half g_suT16[MAT];
__device__ __half g_sdT16[MAT];
__device__ __half g_x16[NTOK * DDIM];    // fp16 activations
__device__ __half g_h16[(size_t)NGRP * NTOK * FDIM];
__device__ __half g_eoh[(size_t)NGRP * NTOK * DDIM];   // expert outputs, fp16
__device__ int    g_cnt[NEXP];
__device__ int    g_tok[NEXP * NTOK];
__device__ int    g_slot_e[NTOK * 2];
__device__ int    g_slot_p[NTOK * 2];
__device__ float  g_slot_w[NTOK * 2];

// ---------------- helpers ---------------------------------------------------
__device__ __forceinline__ uint32_t s2u(const void* p) {
    uint32_t a;
    asm("{ .reg .u64 t; cvta.to.shared.u64 t, %1; cvt.u32.u64 %0, t; }"
        : "=r"(a) : "l"(p));
    return a;
}

__device__ __forceinline__ void cp16(uint32_t dst, const void* src) {
    asm volatile("cp.async.cg.shared.global [%0], [%1], 16;"
                 :: "r"(dst), "l"(src) : "memory");
}
#define CP_COMMIT() asm volatile("cp.async.commit_group;" ::: "memory")
#define CP_WAIT1()  asm volatile("cp.async.wait_group 1;" ::: "memory")

// m16n8k16 fp16 mma, fp32 accumulate (arch-agnostic; sm_80+)
#define MMA16(c, a, b0, b1)                                                  \
    asm volatile("mma.sync.aligned.m16n8k16.row.col.f32.f16.f16.f32 "        \
                 "{%0,%1,%2,%3}, {%4,%5,%6,%7}, {%8,%9}, {%0,%1,%2,%3};"     \
                 : "+f"((c)[0]), "+f"((c)[1]), "+f"((c)[2]), "+f"((c)[3])    \
                 : "r"((a)[0]), "r"((a)[1]), "r"((a)[2]), "r"((a)[3]),       \
                   "r"(b0), "r"(b1))

#define STRH 72          // smem row stride in halves: 144 B, conflict-free
#define KC   64          // K elements per chunk
#define NCHUNK (DDIM / KC)

// Both GEMMs: M=128 tiles, stage = 18432 halves = 36864 B, 3 stages = 110592 B
// -> 2 CTAs/SM
#define G_STAGE_H  18432
#define G1_BG_OFF  9216      // A 128x72 = 9216 halves
#define G1_BU_OFF  13824     // Bg 64x72 = 4608
#define G2_B_OFF   9216      // B 128x72 = 9216
#define G_SMEM     (3 * G_STAGE_H * 2)

__device__ __forceinline__ uint32_t ldh2(const __half* p) {
    return *reinterpret_cast<const uint32_t*>(p);
}

// ---------------- fused pre-kernel -------------------------------------------
// blocks [0, 256)          : router, 32 tokens/block (rw transpose amortized 4x)
//                            + fused x fp32->fp16 conversion
// blocks [256, 256+4608)   : STRIP transpose (32 rows x 128 cols) of wg/wu/sg/su
__global__ void __launch_bounds__(256) k_pre(
    const float* __restrict__ x,  const float* __restrict__ rw,
    const float* __restrict__ wg, const float* __restrict__ wu,
    const float* __restrict__ sg, const float* __restrict__ su) {
    __shared__ float sbuf[8192];          // 32 KB, used by both paths
    int bid = blockIdx.x, tid = threadIdx.x;

    if (bid < 256) {
        // ---- router path: 32 tokens per block ----
        const float4* rw4 = reinterpret_cast<const float4*>(rw);
        #pragma unroll
        for (int k = 0; k < 8; k++) {
            int i = tid + 256 * k;        // float4 index, 0..2047
            float4 v = rw4[i];
            int d = i >> 1, eb = (i & 1) * 4;
            sbuf[(eb + 0) * 1024 + d] = v.x;
            sbuf[(eb + 1) * 1024 + d] = v.y;
            sbuf[(eb + 2) * 1024 + d] = v.z;
            sbuf[(eb + 3) * 1024 + d] = v.w;
        }
        __syncthreads();

        int lid = tid & 31;
        #pragma unroll
        for (int tg = 0; tg < 4; tg++) {
            int t = bid * 32 + tg * 8 + (tid >> 5);
            const float4* x4 = reinterpret_cast<const float4*>(x + (size_t)t * DDIM);
            __half* xr16 = g_x16 + (size_t)t * DDIM;
            float acc[NEXP];
            #pragma unroll
            for (int e = 0; e < NEXP; e++) acc[e] = 0.f;
            #pragma unroll
            for (int it = 0; it < 8; it++) {
                int idx = lid + it * 32;
                float4 xv = x4[idx];
                __half2 h0 = __floats2half2_rn(xv.x, xv.y);
                __half2 h1 = __floats2half2_rn(xv.z, xv.w);
                *reinterpret_cast<__half2*>(xr16 + 4 * idx)     = h0;
                *reinterpret_cast<__half2*>(xr16 + 4 * idx + 2) = h1;
                #pragma unroll
                for (int e = 0; e < NEXP; e++) {
                    float4 w = *reinterpret_cast<const float4*>(&sbuf[e * 1024 + 4 * idx]);
                    acc[e] += xv.x * w.x + xv.y * w.y + xv.z * w.z + xv.w * w.w;
                }
            }
            #pragma unroll
            for (int e = 0; e < NEXP; e++) {
                #pragma unroll
                for (int off = 16; off > 0; off >>= 1)
                    acc[e] += __shfl_xor_sync(0xffffffffu, acc[e], off);
            }
            if (lid == 0) {
                int i0 = 0;
                #pragma unroll
                for (int e = 1; e < NEXP; e++) if (acc[e] > acc[i0]) i0 = e;
                int i1 = (i0 == 0) ? 1 : 0;
                #pragma unroll
                for (int e = 0; e < NEXP; e++) if (e != i0 && acc[e] > acc[i1]) i1 = e;
                float mx = acc[i0];
                float s = 0.f;
                #pragma unroll
                for (int e = 0; e < NEXP; e++) s += expf(acc[e] - mx);
                float p0 = expf(acc[i0] - mx) / s, p1 = expf(acc[i1] - mx) / s;
                float den = p0 + p1 + 1e-9f;
                float w0 = p0 / den, w1 = p1 / den;
                int q0 = atomicAdd(&g_cnt[i0], 1);
                int q1 = atomicAdd(&g_cnt[i1], 1);
                g_tok[i0 * NTOK + q0] = t;
                g_tok[i1 * NTOK + q1] = t;
                g_slot_e[2 * t] = i0;     g_slot_p[2 * t] = q0;     g_slot_w[2 * t] = w0;
                g_slot_e[2 * t + 1] = i1; g_slot_p[2 * t + 1] = q1; g_slot_w[2 * t + 1] = w1;
            }
        }
    } else {
        // ---- strip transpose: 32 rows x 128 cols, float4 loads, half2 stores
        int b = bid - 256;                     // 0..4607
        int z = b >> 8, ti = b & 255;          // 256 strips per matrix
        const float* src; __half* dst;
        if (z < 8)       { src = wg + (size_t)z * MAT;       dst = g_wgT16 + (size_t)z * MAT; }
        else if (z < 16) { src = wu + (size_t)(z - 8) * MAT; dst = g_wuT16 + (size_t)(z - 8) * MAT; }
        else if (z == 16){ src = sg; dst = g_sgT16; }
        else             { src = su; dst = g_suT16; }
        int bx = (ti & 7) * 128, by = (ti >> 3) * 32;
        int r = tid >> 3, c4 = tid & 7;
        #pragma unroll
        for (int i = 0; i < 4; i++) {
            int cbase = 4 * c4 + 32 * i;
            float4 v = *reinterpret_cast<const float4*>(
                src + (size_t)(by + r) * 1024 + bx + cbase);
            sbuf[(cbase + 0) * 33 + r] = v.x;
            sbuf[(cbase + 1) * 33 + r] = v.y;
            sbuf[(cbase + 2) * 33 + r] = v.z;
            sbuf[(cbase + 3) * 33 + r] = v.w;
        }
        __syncthreads();
        int cc = tid >> 3, rp2 = (tid & 7) * 2;
        #pragma unroll
        for (int ib = 0; ib < 4; ib++) {
            int cf = cc + 32 * ib;
            #pragma unroll
            for (int i = 0; i < 2; i++) {
                int rr = rp2 + 16 * i;
                __half2 h = __floats2half2_rn(sbuf[cf * 33 + rr], sbuf[cf * 33 + rr + 1]);
                *reinterpret_cast<__half2*>(dst + (size_t)(bx + cf) * 1024 + by + rr) = h;
            }
        }
    }
}

// ---------------- GEMM1: h = silu(A@Wg) * (A@Wu), fp16 mma -------------------
// CTA 256 thr (4M x 2N warps), tile M=128 N=64, warp tile 32x32 dual.
// 3-stage pipeline, 2 CTAs/SM. Prologue: each of the 9216 CTAs transposes ONE
// 32x32 wd/sd tile (grid size == tile count); consumed only by k_gemm2.
__global__ void __launch_bounds__(256, 2) k_gemm1(const float* __restrict__ wd,
                                                  const float* __restrict__ sd) {
    int g = blockIdx.z, mt = blockIdx.y, nt = blockIdx.x;
    int tid = threadIdx.x;
    extern __shared__ __half smh[];

    // ---- deferred wd/sd transpose (1 tile per CTA, before early-out) ----
    {
        int id = (g * 64 + mt) * 16 + nt;      // 0..9215 == tile id
        int m2 = id >> 10, ti = id & 1023;
        const float* src = (m2 < 8) ? wd + (size_t)m2 * MAT : sd;
        __half* dst = (m2 < 8) ? g_wdT16 + (size_t)m2 * MAT : g_sdT16;
        float* sbuf = reinterpret_cast<float*>(smh);
        int bx = (ti & 31) * 32, by = ((ti >> 5) & 31) * 32;
        int r = tid >> 3, c4 = tid & 7;
        float4 v = *reinterpret_cast<const float4*>(
            src + (size_t)(by + r) * 1024 + bx + 4 * c4);
        sbuf[(4 * c4 + 0) * 33 + r] = v.x;
        sbuf[(4 * c4 + 1) * 33 + r] = v.y;
        sbuf[(4 * c4 + 2) * 33 + r] = v.z;
        sbuf[(4 * c4 + 3) * 33 + r] = v.w;
        __syncthreads();
        int cc = tid >> 3, rp2 = (tid & 7) * 2;
        #pragma unroll
        for (int i = 0; i < 2; i++) {
            int rr = rp2 + 16 * i;
            __half2 h = __floats2half2_rn(sbuf[cc * 33 + rr], sbuf[cc * 33 + rr + 1]);
            *reinterpret_cast<__half2*>(dst + (size_t)(bx + cc) * 1024 + by + rr) = h;
        }
        __syncthreads();   // all smem reads done before cp.async reuses stage 0
    }

    int cnt = (g == NEXP) ? NTOK : g_cnt[g];
    if (mt * 128 >= cnt) return;

    uint32_t sb = s2u(smh);
    int lane = tid & 31, wid = tid >> 5;
    int wm = wid >> 1, wn = wid & 1;         // 4M x 2N
    int lq = lane >> 2, lr = lane & 3;
    int trow = tid >> 3, tcol = (tid & 7) * 8;   // halves

    uint32_t offA[4];
    #pragma unroll
    for (int i = 0; i < 4; i++) {
        int r = mt * 128 + trow + 32 * i;
        int row;
        if (g < NEXP) row = g_tok[g * NTOK + (r < cnt ? r : cnt - 1)];
        else          row = r;
        offA[i] = (uint32_t)row * DDIM + tcol;
    }
    const __half* gb = (g < NEXP) ? g_wgT16 + (size_t)g * MAT : g_sgT16;
    const __half* ub = (g < NEXP) ? g_wuT16 + (size_t)g * MAT : g_suT16;
    uint32_t ncol0 = (uint32_t)nt * 64;

    auto load_stage = [&](int s, int c) {
        uint32_t base = sb + (uint32_t)s * (G_STAGE_H * 2);
        int k0 = c * KC;
        #pragma unroll
        for (int i = 0; i < 4; i++)
            cp16(base + (uint32_t)((trow + 32 * i) * STRH + tcol) * 2,
                 g_x16 + offA[i] + k0);
        #pragma unroll
        for (int i = 0; i < 2; i++) {
            int r = trow + 32 * i;
            uint32_t d = (uint32_t)(r * STRH + tcol) * 2;
            cp16(base + G1_BG_OFF * 2 + d,
                 gb + (size_t)(ncol0 + r) * DDIM + k0 + tcol);
            cp16(base + G1_BU_OFF * 2 + d,
                 ub + (size_t)(ncol0 + r) * DDIM + k0 + tcol);
        }
    };

    float ag[2][4][4], au[2][4][4];
    #pragma unroll
    for (int mi = 0; mi < 2; mi++)
        #pragma unroll
        for (int ni = 0; ni < 4; ni++)
            #pragma unroll
            for (int q = 0; q < 4; q++) { ag[mi][ni][q] = 0.f; au[mi][ni][q] = 0.f; }

    load_stage(0, 0); CP_COMMIT();
    load_stage(1, 1); CP_COMMIT();
    for (int c = 0; c < NCHUNK; c++) {
        CP_WAIT1();
        __syncthreads();
        if (c + 2 < NCHUNK) load_stage((c + 2) % 3, c + 2);
        CP_COMMIT();
        const __half* As  = smh + (c % 3) * G_STAGE_H;
        const __half* Bgs = As + G1_BG_OFF;
        const __half* Bus = As + G1_BU_OFF;
        #pragma unroll
        for (int ks = 0; ks < 4; ks++) {
            int kkh = ks * 16 + 2 * lr;
            uint32_t a[2][4];
            #pragma unroll
            for (int mi = 0; mi < 2; mi++) {
                const __half* Ap = As + (wm * 32 + mi * 16 + lq) * STRH + kkh;
                a[mi][0] = ldh2(Ap);
                a[mi][1] = ldh2(Ap + 8 * STRH);
                a[mi][2] = ldh2(Ap + 8);
                a[mi][3] = ldh2(Ap + 8 * STRH + 8);
            }
            #pragma unroll
            for (int ni = 0; ni < 4; ni++) {
                const __half* Bp = Bgs + (wn * 32 + ni * 8 + lq) * STRH + kkh;
                const __half* Up = Bus + (wn * 32 + ni * 8 + lq) * STRH + kkh;
                uint32_t bg0 = ldh2(Bp), bg1 = ldh2(Bp + 8);
                uint32_t bu0 = ldh2(Up), bu1 = ldh2(Up + 8);
                #pragma unroll
                for (int mi = 0; mi < 2; mi++) {
                    MMA16(ag[mi][ni], a[mi], bg0, bg1);
                    MMA16(au[mi][ni], a[mi], bu0, bu1);
                }
            }
        }
    }

    // fused SwiGLU epilogue -> g_h16 (fp16 for GEMM2)
    __half* hp = g_h16 + ((size_t)g * NTOK + mt * 128) * FDIM + nt * 64;
    #pragma unroll
    for (int mi = 0; mi < 2; mi++) {
        int r0 = wm * 32 + mi * 16 + lq;
        #pragma unroll
        for (int ni = 0; ni < 4; ni++) {
            int cc = wn * 32 + ni * 8 + lr * 2;
            float gv, uv, v0, v1;
            gv = ag[mi][ni][0]; uv = au[mi][ni][0];
            v0 = gv / (1.f + __expf(-gv)) * uv;
            gv = ag[mi][ni][1]; uv = au[mi][ni][1];
            v1 = gv / (1.f + __expf(-gv)) * uv;
            *reinterpret_cast<__half2*>(hp + (size_t)r0 * FDIM + cc) = __floats2half2_rn(v0, v1);
            gv = ag[mi][ni][2]; uv = au[mi][ni][2];
            v0 = gv / (1.f + __expf(-gv)) * uv;
            gv = ag[mi][ni][3]; uv = au[mi][ni][3];
            v1 = gv / (1.f + __expf(-gv)) * uv;
            *reinterpret_cast<__half2*>(hp + (size_t)(r0 + 8) * FDIM + cc) = __floats2half2_rn(v0, v1);
        }
    }
}

// ---------------- GEMM2: eo = h @ Wd, fp16 mma, fp16 store --------------------
// CTA 256 thr (4M x 2N), tile M=128 N=128, warp tile 32x64, 2 CTAs/SM.
__global__ void __launch_bounds__(256, 2) k_gemm2() {
    int g = blockIdx.z, mt = blockIdx.y, nt = blockIdx.x;
    int cnt = (g == NEXP) ? NTOK : g_cnt[g];
    if (mt * 128 >= cnt) return;

    extern __shared__ __half smh[];
    uint32_t sb = s2u(smh);
    int tid = threadIdx.x, lane = tid & 31, wid = tid >> 5;
    int wm = wid >> 1, wn = wid & 1;
    int lq = lane >> 2, lr = lane & 3;
    int trow = tid >> 3, tcol = (tid & 7) * 8;

    const __half* abase = g_h16 + ((size_t)g * NTOK + mt * 128) * FDIM;
    const __half* bbase = (g < NEXP) ? g_wdT16 + (size_t)g * MAT : g_sdT16;
    uint32_t ncol0 = (uint32_t)nt * 128;

    auto load_stage = [&](int s, int c) {
        uint32_t base = sb + (uint32_t)s * (G_STAGE_H * 2);
        int k0 = c * KC;
        #pragma unroll
        for (int i = 0; i < 4; i++) {
            int r = trow + 32 * i;
            cp16(base + (uint32_t)(r * STRH + tcol) * 2,
                 abase + (size_t)r * FDIM + k0 + tcol);
        }
        #pragma unroll
        for (int i = 0; i < 4; i++) {
            int r = trow + 32 * i;
            cp16(base + G2_B_OFF * 2 + (uint32_t)(r * STRH + tcol) * 2,
                 bbase + (size_t)(ncol0 + r) * FDIM + k0 + tcol);
        }
    };

    float ac[2][8][4];
    #pragma unroll
    for (int mi = 0; mi < 2; mi++)
        #pragma unroll
        for (int ni = 0; ni < 8; ni++)
            #pragma unroll
            for (int q = 0; q < 4; q++) ac[mi][ni][q] = 0.f;

    load_stage(0, 0); CP_COMMIT();
    load_stage(1, 1); CP_COMMIT();
    for (int c = 0; c < NCHUNK; c++) {
        CP_WAIT1();
        __syncthreads();
        if (c + 2 < NCHUNK) load_stage((c + 2) % 3, c + 2);
        CP_COMMIT();
        const __half* As = smh + (c % 3) * G_STAGE_H;
        const __half* Bs = As + G2_B_OFF;
        #pragma unroll
        for (int ks = 0; ks < 4; ks++) {
            int kkh = ks * 16 + 2 * lr;
            uint32_t a[2][4];
            #pragma unroll
            for (int mi = 0; mi < 2; mi++) {
                const __half* Ap = As + (wm * 32 + mi * 16 + lq) * STRH + kkh;
                a[mi][0] = ldh2(Ap);
                a[mi][1] = ldh2(Ap + 8 * STRH);
                a[mi][2] = ldh2(Ap + 8);
                a[mi][3] = ldh2(Ap + 8 * STRH + 8);
            }
            #pragma unroll
            for (int ni = 0; ni < 8; ni++) {
                const __half* Bp = Bs + (wn * 64 + ni * 8 + lq) * STRH + kkh;
                uint32_t b0 = ldh2(Bp), b1 = ldh2(Bp + 8);
                #pragma unroll
                for (int mi = 0; mi < 2; mi++) MMA16(ac[mi][ni], a[mi], b0, b1);
            }
        }
    }

    __half* ep = g_eoh + ((size_t)g * NTOK + mt * 128) * DDIM + nt * 128;
    #pragma unroll
    for (int mi = 0; mi < 2; mi++) {
        int r0 = wm * 32 + mi * 16 + lq;
        #pragma unroll
        for (int ni = 0; ni < 8; ni++) {
            int cc = wn * 64 + ni * 8 + lr * 2;
            *reinterpret_cast<__half2*>(ep + (size_t)r0 * DDIM + cc) =
                __floats2half2_rn(ac[mi][ni][0], ac[mi][ni][1]);
            *reinterpret_cast<__half2*>(ep + (size_t)(r0 + 8) * DDIM + cc) =
                __floats2half2_rn(ac[mi][ni][2], ac[mi][ni][3]);
        }
    }
}

// ---------------- combine: out = shared + w0*eo0 + w1*eo1 --------------------
// 128 threads/token, 16B vector loads (3x ld.128 + 2x st.128 per thread).
__global__ void __launch_bounds__(128) k_combine(float* __restrict__ out) {
    int t = blockIdx.x;
    int e0 = g_slot_e[2 * t], e1 = g_slot_e[2 * t + 1];
    int p0 = g_slot_p[2 * t], p1 = g_slot_p[2 * t + 1];
    float w0 = g_slot_w[2 * t], w1 = g_slot_w[2 * t + 1];
    const uint4* sh = reinterpret_cast<const uint4*>(g_eoh + ((size_t)NEXP * NTOK + t) * DDIM);
    const uint4* a  = reinterpret_cast<const uint4*>(g_eoh + ((size_t)e0 * NTOK + p0) * DDIM);
    const uint4* b  = reinterpret_cast<const uint4*>(g_eoh + ((size_t)e1 * NTOK + p1) * DDIM);
    float4* o = reinterpret_cast<float4*>(out + (size_t)t * DDIM);
    int i = threadIdx.x;      // each thread: 8 halves (16 B) per array
    uint4 sv = sh[i], av = a[i], bv = b[i];

    const uint32_t* sp = reinterpret_cast<const uint32_t*>(&sv);
    const uint32_t* ap = reinterpret_cast<const uint32_t*>(&av);
    const uint32_t* bp = reinterpret_cast<const uint32_t*>(&bv);
    float4 o0, o1;
    float* op = reinterpret_cast<float*>(&o0);   // o0,o1 contiguous? not guaranteed
    float res[8];
    #pragma unroll
    for (int j = 0; j < 4; j++) {
        float2 s2 = __half22float2(*reinterpret_cast<const __half2*>(&sp[j]));
        float2 a2 = __half22float2(*reinterpret_cast<const __half2*>(&ap[j]));
        float2 b2 = __half22float2(*reinterpret_cast<const __half2*>(&bp[j]));
        res[2 * j]     = s2.x + w0 * a2.x + w1 * b2.x;
        res[2 * j + 1] = s2.y + w0 * a2.y + w1 * b2.y;
    }
    o0 = make_float4(res[0], res[1], res[2], res[3]);
    o1 = make_float4(res[4], res[5], res[6], res[7]);
    o[2 * i]     = o0;
    o[2 * i + 1] = o1;
    (void)op;
}

// ---------------- launch -----------------------------------------------------
extern "C" void kernel_launch(void* const* d_in, const int* in_sizes, int n_in,
                              void* d_out, int out_size) {
    const float* x  = (const float*)d_in[0];
    const float* rw = (const float*)d_in[1];
    const float* sg = (const float*)d_in[2];
    const float* su = (const float*)d_in[3];
    const float* sd = (const float*)d_in[4];
    const float* wg = (const float*)d_in[5];
    const float* wu = (const float*)d_in[6];
    const float* wd = (const float*)d_in[7];
    float* out = (float*)d_out;

    cudaFuncSetAttribute(k_gemm1, cudaFuncAttributeMaxDynamicSharedMemorySize, G_SMEM);
    cudaFuncSetAttribute(k_gemm2, cudaFuncAttributeMaxDynamicSharedMemorySize, G_SMEM);

    void* cntp = nullptr;
    cudaGetSymbolAddress(&cntp, g_cnt);
    cudaMemsetAsync(cntp, 0, NEXP * sizeof(int));

    k_pre<<<256 + 4608, 256>>>(x, rw, wg, wu, sg, su);
    k_gemm1<<<dim3(16, 64, NGRP), 256, G_SMEM>>>(wd, sd);
    k_gemm2<<<dim3(8, 64, NGRP), 256, G_SMEM>>>();
    k_combine<<<NTOK, 128>>>(out);
}

// round 16
// speedup vs baseline: 1.0749x; 1.0749x over previous
#include <cuda_runtime.h>
#include <cuda_fp16.h>
#include <cstdint>
#include <math.h>

#define NTOK 8192
#define DDIM 1024
#define FDIM 1024
#define NEXP 8
#define NGRP 9
#define MAT  (DDIM * FDIM)

// ---------------- scratch (device globals; no runtime allocation) ----------
__device__ __half g_wgT16[NEXP * MAT];   // [e][f][d]  (B^T for GEMM1 gate)
__device__ __half g_wuT16[NEXP * MAT];   // [e][f][d]
__device__ __half g_wdT16[NEXP * MAT];   // [e][d][f]  (B^T for GEMM2)
__device__ __half g_sgT16[MAT];
__device__ __half g_suT16[MAT];
__device__ __half g_sdT16[MAT];
__device__ __half g_x16[NTOK * DDIM];    // fp16 activations
__device__ __half g_h16[(size_t)NGRP * NTOK * FDIM];
__device__ __half g_eoh[(size_t)NGRP * NTOK * DDIM];   // expert outputs, fp16
__device__ int    g_cnt[NEXP];
__device__ int    g_tok[NEXP * NTOK];
__device__ int    g_slot_e[NTOK * 2];
__device__ int    g_slot_p[NTOK * 2];
__device__ float  g_slot_w[NTOK * 2];

// ---------------- helpers ---------------------------------------------------
__device__ __forceinline__ uint32_t s2u(const void* p) {
    uint32_t a;
    asm("{ .reg .u64 t; cvta.to.shared.u64 t, %1; cvt.u32.u64 %0, t; }"
        : "=r"(a) : "l"(p));
    return a;
}

__device__ __forceinline__ void cp16(uint32_t dst, const void* src) {
    asm volatile("cp.async.cg.shared.global [%0], [%1], 16;"
                 :: "r"(dst), "l"(src) : "memory");
}
#define CP_COMMIT() asm volatile("cp.async.commit_group;" ::: "memory")
#define CP_WAIT1()  asm volatile("cp.async.wait_group 1;" ::: "memory")

// m16n8k16 fp16 mma, fp32 accumulate (arch-agnostic; sm_80+)
#define MMA16(c, a, b0, b1)                                                  \
    asm volatile("mma.sync.aligned.m16n8k16.row.col.f32.f16.f16.f32 "        \
                 "{%0,%1,%2,%3}, {%4,%5,%6,%7}, {%8,%9}, {%0,%1,%2,%3};"     \
                 : "+f"((c)[0]), "+f"((c)[1]), "+f"((c)[2]), "+f"((c)[3])    \
                 : "r"((a)[0]), "r"((a)[1]), "r"((a)[2]), "r"((a)[3]),       \
                   "r"(b0), "r"(b1))

#define STRH 72          // smem row stride in halves: 144 B, conflict-free
#define KC   64          // K elements per chunk
#define NCHUNK (DDIM / KC)

// Both GEMMs: M=128 tiles, stage = 18432 halves = 36864 B, 3 stages = 110592 B
// -> 2 CTAs/SM
#define G_STAGE_H  18432
#define G1_BG_OFF  9216      // A 128x72 = 9216 halves
#define G1_BU_OFF  13824     // Bg 64x72 = 4608
#define G2_B_OFF   9216      // B 128x72 = 9216
#define G_SMEM     (3 * G_STAGE_H * 2)

__device__ __forceinline__ uint32_t ldh2(const __half* p) {
    return *reinterpret_cast<const uint32_t*>(p);
}

// ---------------- fused pre-kernel -------------------------------------------
// blocks [0, 1024)          : router (8 tokens/block) + x fp32->fp16
// blocks [1024, 1024+4608)  : STRIP transpose (32 rows x 128 cols) of wg/wu/sg/su
__global__ void __launch_bounds__(256) k_pre(
    const float* __restrict__ x,  const float* __restrict__ rw,
    const float* __restrict__ wg, const float* __restrict__ wu,
    const float* __restrict__ sg, const float* __restrict__ su) {
    __shared__ float sbuf[8192];          // 32 KB, used by both paths
    int bid = blockIdx.x, tid = threadIdx.x;

    if (bid < 1024) {
        // ---- router path ----
        const float4* rw4 = reinterpret_cast<const float4*>(rw);
        #pragma unroll
        for (int k = 0; k < 8; k++) {
            int i = tid + 256 * k;        // float4 index, 0..2047
            float4 v = rw4[i];
            int d = i >> 1, eb = (i & 1) * 4;
            sbuf[(eb + 0) * 1024 + d] = v.x;
            sbuf[(eb + 1) * 1024 + d] = v.y;
            sbuf[(eb + 2) * 1024 + d] = v.z;
            sbuf[(eb + 3) * 1024 + d] = v.w;
        }
        __syncthreads();

        int t = bid * 8 + (tid >> 5);
        int lid = tid & 31;
        const float4* x4 = reinterpret_cast<const float4*>(x + (size_t)t * DDIM);
        __half* xr16 = g_x16 + (size_t)t * DDIM;
        float acc[NEXP];
        #pragma unroll
        for (int e = 0; e < NEXP; e++) acc[e] = 0.f;
        #pragma unroll
        for (int it = 0; it < 8; it++) {
            int idx = lid + it * 32;
            float4 xv = x4[idx];
            __half2 h0 = __floats2half2_rn(xv.x, xv.y);
            __half2 h1 = __floats2half2_rn(xv.z, xv.w);
            *reinterpret_cast<__half2*>(xr16 + 4 * idx)     = h0;
            *reinterpret_cast<__half2*>(xr16 + 4 * idx + 2) = h1;
            #pragma unroll
            for (int e = 0; e < NEXP; e++) {
                float4 w = *reinterpret_cast<const float4*>(&sbuf[e * 1024 + 4 * idx]);
                acc[e] += xv.x * w.x + xv.y * w.y + xv.z * w.z + xv.w * w.w;
            }
        }
        #pragma unroll
        for (int e = 0; e < NEXP; e++) {
            #pragma unroll
            for (int off = 16; off > 0; off >>= 1)
                acc[e] += __shfl_xor_sync(0xffffffffu, acc[e], off);
        }
        if (lid == 0) {
            int i0 = 0;
            #pragma unroll
            for (int e = 1; e < NEXP; e++) if (acc[e] > acc[i0]) i0 = e;
            int i1 = (i0 == 0) ? 1 : 0;
            #pragma unroll
            for (int e = 0; e < NEXP; e++) if (e != i0 && acc[e] > acc[i1]) i1 = e;
            float mx = acc[i0];
            float s = 0.f;
            #pragma unroll
            for (int e = 0; e < NEXP; e++) s += expf(acc[e] - mx);
            float p0 = expf(acc[i0] - mx) / s, p1 = expf(acc[i1] - mx) / s;
            float den = p0 + p1 + 1e-9f;
            float w0 = p0 / den, w1 = p1 / den;
            int q0 = atomicAdd(&g_cnt[i0], 1);
            int q1 = atomicAdd(&g_cnt[i1], 1);
            g_tok[i0 * NTOK + q0] = t;
            g_tok[i1 * NTOK + q1] = t;
            g_slot_e[2 * t] = i0;     g_slot_p[2 * t] = q0;     g_slot_w[2 * t] = w0;
            g_slot_e[2 * t + 1] = i1; g_slot_p[2 * t + 1] = q1; g_slot_w[2 * t + 1] = w1;
        }
    } else {
        // ---- strip transpose: 32 rows x 128 cols, float4 loads, half2 stores
        int b = bid - 1024;                    // 0..4607
        int z = b >> 8, ti = b & 255;          // 256 strips per matrix
        const float* src; __half* dst;
        if (z < 8)       { src = wg + (size_t)z * MAT;       dst = g_wgT16 + (size_t)z * MAT; }
        else if (z < 16) { src = wu + (size_t)(z - 8) * MAT; dst = g_wuT16 + (size_t)(z - 8) * MAT; }
        else if (z == 16){ src = sg; dst = g_sgT16; }
        else             { src = su; dst = g_suT16; }
        int bx = (ti & 7) * 128, by = (ti >> 3) * 32;
        int r = tid >> 3, c4 = tid & 7;
        #pragma unroll
        for (int i = 0; i < 4; i++) {
            int cbase = 4 * c4 + 32 * i;
            float4 v = *reinterpret_cast<const float4*>(
                src + (size_t)(by + r) * 1024 + bx + cbase);
            sbuf[(cbase + 0) * 33 + r] = v.x;
            sbuf[(cbase + 1) * 33 + r] = v.y;
            sbuf[(cbase + 2) * 33 + r] = v.z;
            sbuf[(cbase + 3) * 33 + r] = v.w;
        }
        __syncthreads();
        int cc = tid >> 3, rp2 = (tid & 7) * 2;
        #pragma unroll
        for (int ib = 0; ib < 4; ib++) {
            int cf = cc + 32 * ib;
            #pragma unroll
            for (int i = 0; i < 2; i++) {
                int rr = rp2 + 16 * i;
                __half2 h = __floats2half2_rn(sbuf[cf * 33 + rr], sbuf[cf * 33 + rr + 1]);
                *reinterpret_cast<__half2*>(dst + (size_t)(bx + cf) * 1024 + by + rr) = h;
            }
        }
    }
}

// ---------------- GEMM1: h = silu(A@Wg) * (A@Wu), fp16 mma -------------------
// CTA 256 thr (4M x 2N warps), tile M=128 N=64, warp tile 32x32 dual.
// 3-stage pipeline, 2 CTAs/SM. Prologue: each of the 9216 CTAs transposes ONE
// 32x32 wd/sd tile (grid size == tile count); consumed only by k_gemm2.
__global__ void __launch_bounds__(256, 2) k_gemm1(const float* __restrict__ wd,
                                                  const float* __restrict__ sd) {
    int g = blockIdx.z, mt = blockIdx.y, nt = blockIdx.x;
    int tid = threadIdx.x;
    extern __shared__ __half smh[];

    // ---- deferred wd/sd transpose (1 tile per CTA, before early-out) ----
    {
        int id = (g * 64 + mt) * 16 + nt;      // 0..9215 == tile id
        int m2 = id >> 10, ti = id & 1023;
        const float* src = (m2 < 8) ? wd + (size_t)m2 * MAT : sd;
        __half* dst = (m2 < 8) ? g_wdT16 + (size_t)m2 * MAT : g_sdT16;
        float* sbuf = reinterpret_cast<float*>(smh);
        int bx = (ti & 31) * 32, by = ((ti >> 5) & 31) * 32;
        int r = tid >> 3, c4 = tid & 7;
        float4 v = *reinterpret_cast<const float4*>(
            src + (size_t)(by + r) * 1024 + bx + 4 * c4);
        sbuf[(4 * c4 + 0) * 33 + r] = v.x;
        sbuf[(4 * c4 + 1) * 33 + r] = v.y;
        sbuf[(4 * c4 + 2) * 33 + r] = v.z;
        sbuf[(4 * c4 + 3) * 33 + r] = v.w;
        __syncthreads();
        int cc = tid >> 3, rp2 = (tid & 7) * 2;
        #pragma unroll
        for (int i = 0; i < 2; i++) {
            int rr = rp2 + 16 * i;
            __half2 h = __floats2half2_rn(sbuf[cc * 33 + rr], sbuf[cc * 33 + rr + 1]);
            *reinterpret_cast<__half2*>(dst + (size_t)(bx + cc) * 1024 + by + rr) = h;
        }
        __syncthreads();   // all smem reads done before cp.async reuses stage 0
    }

    int cnt = (g == NEXP) ? NTOK : g_cnt[g];
    if (mt * 128 >= cnt) return;

    uint32_t sb = s2u(smh);
    int lane = tid & 31, wid = tid >> 5;
    int wm = wid >> 1, wn = wid & 1;         // 4M x 2N
    int lq = lane >> 2, lr = lane & 3;
    int trow = tid >> 3, tcol = (tid & 7) * 8;   // halves

    uint32_t offA[4];
    #pragma unroll
    for (int i = 0; i < 4; i++) {
        int r = mt * 128 + trow + 32 * i;
        int row;
        if (g < NEXP) row = g_tok[g * NTOK + (r < cnt ? r : cnt - 1)];
        else          row = r;
        offA[i] = (uint32_t)row * DDIM + tcol;
    }
    const __half* gb = (g < NEXP) ? g_wgT16 + (size_t)g * MAT : g_sgT16;
    const __half* ub = (g < NEXP) ? g_wuT16 + (size_t)g * MAT : g_suT16;
    uint32_t ncol0 = (uint32_t)nt * 64;

    auto load_stage = [&](int s, int c) {
        uint32_t base = sb + (uint32_t)s * (G_STAGE_H * 2);
        int k0 = c * KC;
        #pragma unroll
        for (int i = 0; i < 4; i++)
            cp16(base + (uint32_t)((trow + 32 * i) * STRH + tcol) * 2,
                 g_x16 + offA[i] + k0);
        #pragma unroll
        for (int i = 0; i < 2; i++) {
            int r = trow + 32 * i;
            uint32_t d = (uint32_t)(r * STRH + tcol) * 2;
            cp16(base + G1_BG_OFF * 2 + d,
                 gb + (size_t)(ncol0 + r) * DDIM + k0 + tcol);
            cp16(base + G1_BU_OFF * 2 + d,
                 ub + (size_t)(ncol0 + r) * DDIM + k0 + tcol);
        }
    };

    float ag[2][4][4], au[2][4][4];
    #pragma unroll
    for (int mi = 0; mi < 2; mi++)
        #pragma unroll
        for (int ni = 0; ni < 4; ni++)
            #pragma unroll
            for (int q = 0; q < 4; q++) { ag[mi][ni][q] = 0.f; au[mi][ni][q] = 0.f; }

    load_stage(0, 0); CP_COMMIT();
    load_stage(1, 1); CP_COMMIT();
    for (int c = 0; c < NCHUNK; c++) {
        CP_WAIT1();
        __syncthreads();
        if (c + 2 < NCHUNK) load_stage((c + 2) % 3, c + 2);
        CP_COMMIT();
        const __half* As  = smh + (c % 3) * G_STAGE_H;
        const __half* Bgs = As + G1_BG_OFF;
        const __half* Bus = As + G1_BU_OFF;
        #pragma unroll
        for (int ks = 0; ks < 4; ks++) {
            int kkh = ks * 16 + 2 * lr;
            uint32_t a[2][4];
            #pragma unroll
            for (int mi = 0; mi < 2; mi++) {
                const __half* Ap = As + (wm * 32 + mi * 16 + lq) * STRH + kkh;
                a[mi][0] = ldh2(Ap);
                a[mi][1] = ldh2(Ap + 8 * STRH);
                a[mi][2] = ldh2(Ap + 8);
                a[mi][3] = ldh2(Ap + 8 * STRH + 8);
            }
            #pragma unroll
            for (int ni = 0; ni < 4; ni++) {
                const __half* Bp = Bgs + (wn * 32 + ni * 8 + lq) * STRH + kkh;
                const __half* Up = Bus + (wn * 32 + ni * 8 + lq) * STRH + kkh;
                uint32_t bg0 = ldh2(Bp), bg1 = ldh2(Bp + 8);
                uint32_t bu0 = ldh2(Up), bu1 = ldh2(Up + 8);
                #pragma unroll
                for (int mi = 0; mi < 2; mi++) {
                    MMA16(ag[mi][ni], a[mi], bg0, bg1);
                    MMA16(au[mi][ni], a[mi], bu0, bu1);
                }
            }
        }
    }

    // fused SwiGLU epilogue -> g_h16 (fp16 for GEMM2)
    __half* hp = g_h16 + ((size_t)g * NTOK + mt * 128) * FDIM + nt * 64;
    #pragma unroll
    for (int mi = 0; mi < 2; mi++) {
        int r0 = wm * 32 + mi * 16 + lq;
        #pragma unroll
        for (int ni = 0; ni < 4; ni++) {
            int cc = wn * 32 + ni * 8 + lr * 2;
            float gv, uv, v0, v1;
            gv = ag[mi][ni][0]; uv = au[mi][ni][0];
            v0 = gv / (1.f + __expf(-gv)) * uv;
            gv = ag[mi][ni][1]; uv = au[mi][ni][1];
            v1 = gv / (1.f + __expf(-gv)) * uv;
            *reinterpret_cast<__half2*>(hp + (size_t)r0 * FDIM + cc) = __floats2half2_rn(v0, v1);
            gv = ag[mi][ni][2]; uv = au[mi][ni][2];
            v0 = gv / (1.f + __expf(-gv)) * uv;
            gv = ag[mi][ni][3]; uv = au[mi][ni][3];
            v1 = gv / (1.f + __expf(-gv)) * uv;
            *reinterpret_cast<__half2*>(hp + (size_t)(r0 + 8) * FDIM + cc) = __floats2half2_rn(v0, v1);
        }
    }
}

// ---------------- GEMM2: eo = h @ Wd, fp16 mma, fp16 store --------------------
// CTA 256 thr (4M x 2N), tile M=128 N=128, warp tile 32x64, 2 CTAs/SM.
__global__ void __launch_bounds__(256, 2) k_gemm2() {
    int g = blockIdx.z, mt = blockIdx.y, nt = blockIdx.x;
    int cnt = (g == NEXP) ? NTOK : g_cnt[g];
    if (mt * 128 >= cnt) return;

    extern __shared__ __half smh[];
    uint32_t sb = s2u(smh);
    int tid = threadIdx.x, lane = tid & 31, wid = tid >> 5;
    int wm = wid >> 1, wn = wid & 1;
    int lq = lane >> 2, lr = lane & 3;
    int trow = tid >> 3, tcol = (tid & 7) * 8;

    const __half* abase = g_h16 + ((size_t)g * NTOK + mt * 128) * FDIM;
    const __half* bbase = (g < NEXP) ? g_wdT16 + (size_t)g * MAT : g_sdT16;
    uint32_t ncol0 = (uint32_t)nt * 128;

    auto load_stage = [&](int s, int c) {
        uint32_t base = sb + (uint32_t)s * (G_STAGE_H * 2);
        int k0 = c * KC;
        #pragma unroll
        for (int i = 0; i < 4; i++) {
            int r = trow + 32 * i;
            cp16(base + (uint32_t)(r * STRH + tcol) * 2,
                 abase + (size_t)r * FDIM + k0 + tcol);
        }
        #pragma unroll
        for (int i = 0; i < 4; i++) {
            int r = trow + 32 * i;
            cp16(base + G2_B_OFF * 2 + (uint32_t)(r * STRH + tcol) * 2,
                 bbase + (size_t)(ncol0 + r) * FDIM + k0 + tcol);
        }
    };

    float ac[2][8][4];
    #pragma unroll
    for (int mi = 0; mi < 2; mi++)
        #pragma unroll
        for (int ni = 0; ni < 8; ni++)
            #pragma unroll
            for (int q = 0; q < 4; q++) ac[mi][ni][q] = 0.f;

    load_stage(0, 0); CP_COMMIT();
    load_stage(1, 1); CP_COMMIT();
    for (int c = 0; c < NCHUNK; c++) {
        CP_WAIT1();
        __syncthreads();
        if (c + 2 < NCHUNK) load_stage((c + 2) % 3, c + 2);
        CP_COMMIT();
        const __half* As = smh + (c % 3) * G_STAGE_H;
        const __half* Bs = As + G2_B_OFF;
        #pragma unroll
        for (int ks = 0; ks < 4; ks++) {
            int kkh = ks * 16 + 2 * lr;
            uint32_t a[2][4];
            #pragma unroll
            for (int mi = 0; mi < 2; mi++) {
                const __half* Ap = As + (wm * 32 + mi * 16 + lq) * STRH + kkh;
                a[mi][0] = ldh2(Ap);
                a[mi][1] = ldh2(Ap + 8 * STRH);
                a[mi][2] = ldh2(Ap + 8);
                a[mi][3] = ldh2(Ap + 8 * STRH + 8);
            }
            #pragma unroll
            for (int ni = 0; ni < 8; ni++) {
                const __half* Bp = Bs + (wn * 64 + ni * 8 + lq) * STRH + kkh;
                uint32_t b0 = ldh2(Bp), b1 = ldh2(Bp + 8);
                #pragma unroll
                for (int mi = 0; mi < 2; mi++) MMA16(ac[mi][ni], a[mi], b0, b1);
            }
        }
    }

    __half* ep = g_eoh + ((size_t)g * NTOK + mt * 128) * DDIM + nt * 128;
    #pragma unroll
    for (int mi = 0; mi < 2; mi++) {
        int r0 = wm * 32 + mi * 16 + lq;
        #pragma unroll
        for (int ni = 0; ni < 8; ni++) {
            int cc = wn * 64 + ni * 8 + lr * 2;
            *reinterpret_cast<__half2*>(ep + (size_t)r0 * DDIM + cc) =
                __floats2half2_rn(ac[mi][ni][0], ac[mi][ni][1]);
            *reinterpret_cast<__half2*>(ep + (size_t)(r0 + 8) * DDIM + cc) =
                __floats2half2_rn(ac[mi][ni][2], ac[mi][ni][3]);
        }
    }
}

// ---------------- combine: out = shared + w0*eo0 + w1*eo1 --------------------
// 128 threads/token, 16B vector loads (3x ld.128 + 2x st.128 per thread).
__global__ void __launch_bounds__(128) k_combine(float* __restrict__ out) {
    int t = blockIdx.x;
    int e0 = g_slot_e[2 * t], e1 = g_slot_e[2 * t + 1];
    int p0 = g_slot_p[2 * t], p1 = g_slot_p[2 * t + 1];
    float w0 = g_slot_w[2 * t], w1 = g_slot_w[2 * t + 1];
    const uint4* sh = reinterpret_cast<const uint4*>(g_eoh + ((size_t)NEXP * NTOK + t) * DDIM);
    const uint4* a  = reinterpret_cast<const uint4*>(g_eoh + ((size_t)e0 * NTOK + p0) * DDIM);
    const uint4* b  = reinterpret_cast<const uint4*>(g_eoh + ((size_t)e1 * NTOK + p1) * DDIM);
    float4* o = reinterpret_cast<float4*>(out + (size_t)t * DDIM);
    int i = threadIdx.x;      // each thread: 8 halves (16 B) per array
    uint4 sv = sh[i], av = a[i], bv = b[i];

    const uint32_t* sp = reinterpret_cast<const uint32_t*>(&sv);
    const uint32_t* ap = reinterpret_cast<const uint32_t*>(&av);
    const uint32_t* bp = reinterpret_cast<const uint32_t*>(&bv);
    float res[8];
    #pragma unroll
    for (int j = 0; j < 4; j++) {
        float2 s2 = __half22float2(*reinterpret_cast<const __half2*>(&sp[j]));
        float2 a2 = __half22float2(*reinterpret_cast<const __half2*>(&ap[j]));
        float2 b2 = __half22float2(*reinterpret_cast<const __half2*>(&bp[j]));
        res[2 * j]     = s2.x + w0 * a2.x + w1 * b2.x;
        res[2 * j + 1] = s2.y + w0 * a2.y + w1 * b2.y;
    }
    o[2 * i]     = make_float4(res[0], res[1], res[2], res[3]);
    o[2 * i + 1] = make_float4(res[4], res[5], res[6], res[7]);
}

// ---------------- launch -----------------------------------------------------
extern "C" void kernel_launch(void* const* d_in, const int* in_sizes, int n_in,
                              void* d_out, int out_size) {
    const float* x  = (const float*)d_in[0];
    const float* rw = (const float*)d_in[1];
    const float* sg = (const float*)d_in[2];
    const float* su = (const float*)d_in[3];
    const float* sd = (const float*)d_in[4];
    const float* wg = (const float*)d_in[5];
    const float* wu = (const float*)d_in[6];
    const float* wd = (const float*)d_in[7];
    float* out = (float*)d_out;

    cudaFuncSetAttribute(k_gemm1, cudaFuncAttributeMaxDynamicSharedMemorySize, G_SMEM);
    cudaFuncSetAttribute(k_gemm2, cudaFuncAttributeMaxDynamicSharedMemorySize, G_SMEM);

    void* cntp = nullptr;
    cudaGetSymbolAddress(&cntp, g_cnt);
    cudaMemsetAsync(cntp, 0, NEXP * sizeof(int));

    k_pre<<<1024 + 4608, 256>>>(x, rw, wg, wu, sg, su);
    k_gemm1<<<dim3(16, 64, NGRP), 256, G_SMEM>>>(wd, sd);
    k_gemm2<<<dim3(8, 64, NGRP), 256, G_SMEM>>>();
    k_combine<<<NTOK, 128>>>(out);
}